// round 1
// baseline (speedup 1.0000x reference)
#include <cuda_runtime.h>
#include <math.h>

#define Bc 32
#define Tc 64
#define Hc 1024
#define Ec 512
#define Mc 512
#define Vc 32000

// ---------------- scratch (device globals; no allocation allowed) -------------
__device__ float g_si[Bc*Hc];
__device__ float g_yi[Bc*Hc];
__device__ float g_Ua[Bc*Tc*Hc];          // Ua_enc [B,T,H]
__device__ float g_sWa[Bc*Hc];
__device__ float g_e[Bc*Tc];
__device__ float g_xbuf[Bc*(2*Hc+Ec)];    // [yi_emb(512) | context(2048)]
__device__ float g_moin[Bc*(3*Hc+Ec)];    // [si_new(1024) | context(2048) | yi_emb(512)]
__device__ float g_gx[Bc*3*Hc];
__device__ float g_gh[Bc*3*Hc];
__device__ float g_m[Bc*Mc];

typedef unsigned long long ull;

__device__ __forceinline__ ull pk2(float x, float y){
    ull r; asm("mov.b64 %0, {%1, %2};" : "=l"(r) : "f"(x), "f"(y)); return r;
}
__device__ __forceinline__ float2 upk2(ull p){
    float2 f; asm("mov.b64 {%0, %1}, %2;" : "=f"(f.x), "=f"(f.y) : "l"(p)); return f;
}
// packed fp32x2 FMA (Blackwell-only PTX; ptxas never auto-fuses this)
__device__ __forceinline__ void fma2(ull &d, ull a, ull b){
    asm("fma.rn.f32x2 %0, %1, %2, %0;" : "+l"(d) : "l"(a), "l"(b));
}

// ---------------- generic skinny GEMM: out[row, n] = act(A[row,:]·W[n,:] + b) --
// rows = 32 per blockIdx.y group (lane == row). Each warp owns VPW columns.
// act: 0 = none, 1 = tanh, 2 = maxout over column pairs (writes N/2 outputs)
template<int VPW>
__global__ void gemm32(const float* __restrict__ A, const float* __restrict__ W,
                       const float* __restrict__ bias,
                       float* __restrict__ out, float* __restrict__ out2,
                       int K, int lda, int ldo, int ldo2, int act)
{
    const int lane = threadIdx.x & 31;
    const int warp = threadIdx.x >> 5;
    const int row  = blockIdx.y * 32 + lane;
    const int col0 = (blockIdx.x * (blockDim.x >> 5) + warp) * VPW;
    const float* a = A + (size_t)row * lda;
    const float* w = W + (size_t)col0 * K;

    ull acc[VPW];
#pragma unroll
    for (int v = 0; v < VPW; v++) acc[v] = 0ull;

#pragma unroll 2
    for (int k = 0; k < K; k += 4){
        float4 a4 = *(const float4*)(a + k);
        ull a01 = pk2(a4.x, a4.y);
        ull a23 = pk2(a4.z, a4.w);
#pragma unroll
        for (int v = 0; v < VPW; v++){
            float4 w4 = *(const float4*)(w + (size_t)v * K + k);
            fma2(acc[v], pk2(w4.x, w4.y), a01);
            fma2(acc[v], pk2(w4.z, w4.w), a23);
        }
    }

    float res[VPW];
#pragma unroll
    for (int v = 0; v < VPW; v++){
        float2 f = upk2(acc[v]);
        res[v] = f.x + f.y + (bias ? bias[col0 + v] : 0.f);
        if (act == 1) res[v] = tanhf(res[v]);
    }
    if (act == 2){
#pragma unroll
        for (int v = 0; v < VPW; v += 2)
            out[(size_t)row * ldo + (col0 + v) / 2] = fmaxf(res[v], res[v + 1]);
    } else {
#pragma unroll
        for (int v = 0; v < VPW; v++){
            out[(size_t)row * ldo + col0 + v] = res[v];
            if (out2) out2[(size_t)row * ldo2 + col0 + v] = res[v];
        }
    }
}

// ---------------- misc kernels ------------------------------------------------
__global__ void zero_yi_kernel(){
    int i = blockIdx.x * 256 + threadIdx.x;
    if (i < Bc*Hc) g_yi[i] = 0.f;
}

// e[b,t] = sum_a va[a] * tanh(sWa[b,a] + Ua_enc[b,t,a])
__global__ void attn_e_kernel(const float* __restrict__ va){
    int bt = blockIdx.x;            // b*T + t
    int b  = bt >> 6;
    const float* sw = g_sWa + (size_t)b * Hc;
    const float* ua = g_Ua  + (size_t)bt * Hc;
    float p = 0.f;
    for (int a = threadIdx.x; a < Hc; a += blockDim.x)
        p += va[a] * tanhf(sw[a] + ua[a]);
    __shared__ float red[4];
#pragma unroll
    for (int o = 16; o > 0; o >>= 1) p += __shfl_xor_sync(0xffffffffu, p, o);
    if ((threadIdx.x & 31) == 0) red[threadIdx.x >> 5] = p;
    __syncthreads();
    if (threadIdx.x == 0) g_e[bt] = red[0] + red[1] + red[2] + red[3];
}

// softmax over T, write alphas, context[b,f] = sum_t alpha*enc_out
__global__ void attn_ctx_kernel(const float* __restrict__ enc_out,
                                float* __restrict__ alphas, int tstep){
    int b = blockIdx.x;
    __shared__ float sal[Tc];
    __shared__ float sinv;
    if (threadIdx.x == 0){
        float mx = -1e30f;
        for (int t = 0; t < Tc; t++) mx = fmaxf(mx, g_e[b*Tc + t]);
        float s = 0.f;
        for (int t = 0; t < Tc; t++){ float ev = expf(g_e[b*Tc + t] - mx); sal[t] = ev; s += ev; }
        sinv = 1.f / s;
    }
    __syncthreads();
    if (threadIdx.x < Tc) sal[threadIdx.x] *= sinv;
    __syncthreads();
    if (threadIdx.x < Tc)
        alphas[((size_t)b * Tc + tstep) * Tc + threadIdx.x] = sal[threadIdx.x];

    const float4* eo = (const float4*)(enc_out + (size_t)b * Tc * 2 * Hc);
    for (int f4 = threadIdx.x; f4 < (2*Hc)/4; f4 += blockDim.x){
        float4 acc = make_float4(0.f, 0.f, 0.f, 0.f);
        for (int t = 0; t < Tc; t++){
            float al = sal[t];
            float4 ev = eo[(size_t)t * (2*Hc/4) + f4];
            acc.x += al*ev.x; acc.y += al*ev.y; acc.z += al*ev.z; acc.w += al*ev.w;
        }
        int f = f4 * 4;
        *(float4*)&g_xbuf[(size_t)b*(2*Hc+Ec) + Ec + f] = acc;
        *(float4*)&g_moin[(size_t)b*(3*Hc+Ec) + Hc + f] = acc;
    }
}

// PyTorch GRU cell gates -> si_new; mirror into yi and moin[:,0:H]
__global__ void gru_gate_kernel(){
    int i = blockIdx.x * 256 + threadIdx.x;
    if (i >= Bc*Hc) return;
    int b = i >> 10, h = i & (Hc - 1);
    const float* gx = g_gx + (size_t)b * 3 * Hc;
    const float* gh = g_gh + (size_t)b * 3 * Hc;
    float r = 1.f / (1.f + expf(-(gx[h]        + gh[h])));
    float z = 1.f / (1.f + expf(-(gx[Hc + h]   + gh[Hc + h])));
    float n = tanhf(gx[2*Hc + h] + r * gh[2*Hc + h]);
    float s = g_si[i];
    float sn = (1.f - z) * n + z * s;
    g_si[i] = sn;
    g_yi[i] = sn;
    g_moin[(size_t)b * (3*Hc + Ec) + h] = sn;
}

// ---------------- launch ------------------------------------------------------
extern "C" void kernel_launch(void* const* d_in, const int* in_sizes, int n_in,
                              void* d_out, int out_size)
{
    const float* enc_out = (const float*)d_in[0];   // [B,T,2H]
    const float* hidden  = (const float*)d_in[1];   // [2,B,H]
    const float* Ws_w    = (const float*)d_in[2];
    const float* Ws_b    = (const float*)d_in[3];
    const float* emb_w   = (const float*)d_in[4];
    const float* emb_b   = (const float*)d_in[5];
    const float* w_ih    = (const float*)d_in[6];
    const float* w_hh    = (const float*)d_in[7];
    const float* b_ih    = (const float*)d_in[8];
    const float* b_hh    = (const float*)d_in[9];
    const float* Wa      = (const float*)d_in[10];
    const float* Ua      = (const float*)d_in[11];
    const float* va      = (const float*)d_in[12];
    const float* mo_w    = (const float*)d_in[13];
    const float* mo_b    = (const float*)d_in[14];
    const float* fc_w    = (const float*)d_in[15];
    const float* fc_b    = (const float*)d_in[16];

    float* logits = (float*)d_out;                       // [B,T,V]
    float* alphas = logits + (size_t)Bc * Tc * Vc;       // [B,T,T]

    float *psi, *pyi, *pUa, *psWa, *pxbuf, *pmoin, *pgx, *pgh, *pm;
    cudaGetSymbolAddress((void**)&psi,   g_si);
    cudaGetSymbolAddress((void**)&pyi,   g_yi);
    cudaGetSymbolAddress((void**)&pUa,   g_Ua);
    cudaGetSymbolAddress((void**)&psWa,  g_sWa);
    cudaGetSymbolAddress((void**)&pxbuf, g_xbuf);
    cudaGetSymbolAddress((void**)&pmoin, g_moin);
    cudaGetSymbolAddress((void**)&pgx,   g_gx);
    cudaGetSymbolAddress((void**)&pgh,   g_gh);
    cudaGetSymbolAddress((void**)&pm,    g_m);

    // ---- setup: yi=0, si0 = tanh(hidden[1] @ Ws_w^T + Ws_b), Ua_enc precompute
    zero_yi_kernel<<<(Bc*Hc + 255)/256, 256>>>();
    gemm32<4><<<dim3(Hc/32, 1), 256>>>(hidden + Bc*Hc, Ws_w, Ws_b,
                                       psi, nullptr, Hc, Hc, Hc, 0, 1);
    gemm32<8><<<dim3(Hc/64, (Bc*Tc)/32), 256>>>(enc_out, Ua, nullptr,
                                       pUa, nullptr, 2*Hc, 2*Hc, Hc, 0, 0);

    for (int t = 0; t < Tc; t++){
        // sWa = si @ Wa^T
        gemm32<4><<<dim3(Hc/32, 1), 256>>>(psi, Wa, nullptr,
                                           psWa, nullptr, Hc, Hc, Hc, 0, 0);
        // attention energies + softmax/context (alpha -> output)
        attn_e_kernel<<<Bc*Tc, 128>>>(va);
        attn_ctx_kernel<<<Bc, 256>>>(enc_out, alphas, t);
        // yi_emb = yi @ emb_w^T + emb_b  -> xbuf[:,0:E] and moin[:,3H:3H+E]
        gemm32<4><<<dim3(Ec/32, 1), 256>>>(pyi, emb_w, emb_b,
                                           pxbuf, pmoin + 3*Hc,
                                           Hc, Hc, 2*Hc+Ec, 3*Hc+Ec, 0);
        // gx = x @ w_ih^T + b_ih ;  gh = si @ w_hh^T + b_hh
        gemm32<8><<<dim3(3*Hc/64, 1), 256>>>(pxbuf, w_ih, b_ih,
                                           pgx, nullptr, 2*Hc+Ec, 2*Hc+Ec, 3*Hc, 0, 0);
        gemm32<8><<<dim3(3*Hc/64, 1), 256>>>(psi, w_hh, b_hh,
                                           pgh, nullptr, Hc, Hc, 3*Hc, 0, 0);
        // GRU gates -> si/yi/moin[:,0:H]
        gru_gate_kernel<<<(Bc*Hc + 255)/256, 256>>>();
        // maxout GEMM: m = max-pair(moin @ mo_w^T + mo_b)
        gemm32<8><<<dim3(2*Mc/64, 1), 256>>>(pmoin, mo_w, mo_b,
                                           pm, nullptr, 3*Hc+Ec, 3*Hc+Ec, Mc, 0, 2);
        // logits[:, t, :] = m @ fc_w^T + fc_b
        gemm32<8><<<dim3(Vc/64, 1), 256>>>(pm, fc_w, fc_b,
                                           logits + (size_t)t * Vc, nullptr,
                                           Mc, Mc, Tc*Vc, 0, 0);
    }
}

// round 2
// speedup vs baseline: 1.3205x; 1.3205x over previous
#include <cuda_runtime.h>
#include <math.h>

#define Bc 32
#define Tc 64
#define Hc 1024
#define Ec 512
#define Mc 512
#define Vc 32000

// ---------------- scratch (device globals) ------------------------------------
// P4 layout: arr[(k>>2)*128 + b*4 + (k&3)]  (k = feature, b = batch row 0..31)
__device__ float g_siT[Hc*32];
__device__ float g_hidT[Hc*32];
__device__ float g_encT[Bc*Tc*2*Hc];        // enc_out transposed P4, 64 row-groups
__device__ float g_Ua[Bc*Tc*Hc];            // row-major [bt][a]
__device__ float g_sWa[Bc*Hc];              // row-major [b][a]
__device__ float g_e[Bc*Tc];
__device__ float g_xT[(2*Hc+Ec)*32];        // P4: [emb(512) | ctx(2048)]
__device__ float g_moinT[(3*Hc+Ec)*32];     // P4: [si(1024) | ctx(2048) | emb(512)]
__device__ float g_gxT[3*Hc*32];
__device__ float g_ghT[3*Hc*32];
__device__ float g_mT[Mc*32];

typedef unsigned long long ull;

__device__ __forceinline__ ull pk2(float x, float y){
    ull r; asm("mov.b64 %0, {%1, %2};" : "=l"(r) : "f"(x), "f"(y)); return r;
}
__device__ __forceinline__ float2 upk2(ull p){
    float2 f; asm("mov.b64 {%0, %1}, %2;" : "=f"(f.x), "=f"(f.y) : "l"(p)); return f;
}
__device__ __forceinline__ void fma2(ull &d, ull a, ull b){
    asm("fma.rn.f32x2 %0, %1, %2, %0;" : "+l"(d) : "l"(a), "l"(b));
}
__device__ __forceinline__ float tanha(float x){
    float y; asm("tanh.approx.f32 %0, %1;" : "=f"(y) : "f"(x)); return y;
}

// ---------------- row-major [rows][K] -> P4 (row-groups of 32) ----------------
__global__ void to_p4(const float* __restrict__ in, float* __restrict__ out, int K){
    int g = blockIdx.y;
    int n4 = (K >> 2) * 32;                      // float4 slots per group
    for (int idx = blockIdx.x*blockDim.x + threadIdx.x; idx < n4; idx += gridDim.x*blockDim.x){
        int lane = idx & 31, k4 = idx >> 5;
        float4 v = *(const float4*)(in + (size_t)(g*32 + lane)*K + k4*4);
        *(float4*)(out + (size_t)g*K*32 + k4*128 + lane*4) = v;
    }
}

// ---------------- GEMM on P4 activations --------------------------------------
// out[row, col] = act( A_P4[row,:] . W[col,:] + bias[col] )
// MODE 0: P4 store (+ optional dup to out2, pre-offset); MODE 1: row-major via
// smem transpose (ldo = row stride); MODE 2: maxout pairs -> P4.
template<int K, int WARPS, int MODE>
__global__ void gemmP4(const float* __restrict__ A, const float* __restrict__ W,
                       const float* __restrict__ bias,
                       float* __restrict__ out, float* __restrict__ out2,
                       int ldo, int act_tanh)
{
    const int lane = threadIdx.x & 31;
    const int warp = threadIdx.x >> 5;
    const int col0 = (blockIdx.x*WARPS + warp)*8;
    const float* aP = A + (size_t)blockIdx.y*K*32 + lane*4;
    const float* w0 = W + (size_t)col0*K;

    ull acc[8];
#pragma unroll
    for (int v = 0; v < 8; v++) acc[v] = 0ull;

    if (A){
#pragma unroll 2
        for (int k4 = 0; k4 < K/4; k4++){
            float4 a4 = *(const float4*)(aP + k4*128);
            ull a01 = pk2(a4.x, a4.y);
            ull a23 = pk2(a4.z, a4.w);
#pragma unroll
            for (int v = 0; v < 8; v++){
                float4 w4 = *(const float4*)(w0 + (size_t)v*K + k4*4);
                fma2(acc[v], pk2(w4.x, w4.y), a01);
                fma2(acc[v], pk2(w4.z, w4.w), a23);
            }
        }
    }

    float res[8];
#pragma unroll
    for (int v = 0; v < 8; v++){
        float2 f = upk2(acc[v]);
        res[v] = f.x + f.y + (bias ? bias[col0 + v] : 0.f);
        if (act_tanh) res[v] = tanhf(res[v]);
    }

    if (MODE == 0){
        size_t idx = (size_t)(col0 >> 2)*128 + lane*4;
        *(float4*)(out + idx)        = make_float4(res[0], res[1], res[2], res[3]);
        *(float4*)(out + idx + 128)  = make_float4(res[4], res[5], res[6], res[7]);
        if (out2){
            *(float4*)(out2 + idx)       = make_float4(res[0], res[1], res[2], res[3]);
            *(float4*)(out2 + idx + 128) = make_float4(res[4], res[5], res[6], res[7]);
        }
    } else if (MODE == 2){
        float m0 = fmaxf(res[0], res[1]), m1 = fmaxf(res[2], res[3]);
        float m2 = fmaxf(res[4], res[5]), m3 = fmaxf(res[6], res[7]);
        size_t idx = (size_t)(col0 >> 3)*128 + lane*4;   // (col0/2)/4 * 128
        *(float4*)(out + idx) = make_float4(m0, m1, m2, m3);
    } else {
        __shared__ float s[WARPS*8][33];
#pragma unroll
        for (int v = 0; v < 8; v++) s[warp*8 + v][lane] = res[v];
        __syncthreads();
        const int colsB = WARPS*8;
        const int tpr = colsB/8;                       // threads per row
        int row = threadIdx.x / tpr;
        int cst = (threadIdx.x % tpr)*8;
        int colBase = blockIdx.x*colsB;
        size_t obase = (size_t)(blockIdx.y*32 + row)*ldo + colBase + cst;
        float4 o0 = make_float4(s[cst+0][row], s[cst+1][row], s[cst+2][row], s[cst+3][row]);
        float4 o1 = make_float4(s[cst+4][row], s[cst+5][row], s[cst+6][row], s[cst+7][row]);
        *(float4*)(out + obase)     = o0;
        *(float4*)(out + obase + 4) = o1;
    }
}

// ---------------- attention ---------------------------------------------------
// e[b,t] = sum_a va[a] * tanh(sWa[b,a] + Ua[bt,a])
__global__ void attn_e_kernel(const float* __restrict__ va){
    int b  = blockIdx.y;
    int bt = b*Tc + blockIdx.x;
    const float* sw = g_sWa + (size_t)b*Hc;
    const float* ua = g_Ua  + (size_t)bt*Hc;
    float p = 0.f;
    for (int a = threadIdx.x; a < Hc; a += 128)
        p += va[a] * tanha(sw[a] + ua[a]);
    __shared__ float red[4];
#pragma unroll
    for (int o = 16; o > 0; o >>= 1) p += __shfl_xor_sync(0xffffffffu, p, o);
    if ((threadIdx.x & 31) == 0) red[threadIdx.x >> 5] = p;
    __syncthreads();
    if (threadIdx.x == 0) g_e[bt] = red[0] + red[1] + red[2] + red[3];
}

// softmax over T -> alphas; context -> xT (k=E+f) and moinT (k=H+f), P4 scatter
__global__ void attn_ctx_kernel(const float* __restrict__ enc_out,
                                float* __restrict__ alphas, int tstep){
    int b = blockIdx.x;
    __shared__ float sal[Tc];
    __shared__ float sinv;
    if (threadIdx.x == 0){
        float mx = -1e30f;
        for (int t = 0; t < Tc; t++) mx = fmaxf(mx, g_e[b*Tc + t]);
        float s = 0.f;
        for (int t = 0; t < Tc; t++){ float ev = __expf(g_e[b*Tc + t] - mx); sal[t] = ev; s += ev; }
        sinv = 1.f / s;
    }
    __syncthreads();
    if (threadIdx.x < Tc) sal[threadIdx.x] *= sinv;
    __syncthreads();
    if (threadIdx.x < Tc)
        alphas[((size_t)b*Tc + tstep)*Tc + threadIdx.x] = sal[threadIdx.x];

    const float4* eo = (const float4*)(enc_out + (size_t)b*Tc*2*Hc);
    for (int f4 = threadIdx.x; f4 < (2*Hc)/4; f4 += blockDim.x){
        float4 acc = make_float4(0.f, 0.f, 0.f, 0.f);
        for (int t = 0; t < Tc; t++){
            float al = sal[t];
            float4 ev = eo[(size_t)t*(2*Hc/4) + f4];
            acc.x += al*ev.x; acc.y += al*ev.y; acc.z += al*ev.z; acc.w += al*ev.w;
        }
        *(float4*)&g_xT[(size_t)(Ec/4 + f4)*128 + b*4]      = acc;  // k = E + 4*f4
        *(float4*)&g_moinT[(size_t)(Hc/4 + f4)*128 + b*4]   = acc;  // k = H + 4*f4
    }
}

// ---------------- GRU gates (all P4, fully coalesced) -------------------------
__global__ void gru_gate_kernel(){
    int j = blockIdx.x*256 + threadIdx.x;
    if (j >= Hc*32) return;
    float xr = g_gxT[j],             hr = g_ghT[j];
    float xz = g_gxT[j + Hc*32],     hz = g_ghT[j + Hc*32];
    float xn = g_gxT[j + 2*Hc*32],   hn = g_ghT[j + 2*Hc*32];
    float r = 1.f/(1.f + __expf(-(xr + hr)));
    float z = 1.f/(1.f + __expf(-(xz + hz)));
    float n = tanhf(xn + r*hn);
    float s = g_siT[j];
    float sn = (1.f - z)*n + z*s;
    g_siT[j]   = sn;
    g_moinT[j] = sn;
}

// ---------------- launch ------------------------------------------------------
extern "C" void kernel_launch(void* const* d_in, const int* in_sizes, int n_in,
                              void* d_out, int out_size)
{
    const float* enc_out = (const float*)d_in[0];
    const float* hidden  = (const float*)d_in[1];
    const float* Ws_w    = (const float*)d_in[2];
    const float* Ws_b    = (const float*)d_in[3];
    const float* emb_w   = (const float*)d_in[4];
    const float* emb_b   = (const float*)d_in[5];
    const float* w_ih    = (const float*)d_in[6];
    const float* w_hh    = (const float*)d_in[7];
    const float* b_ih    = (const float*)d_in[8];
    const float* b_hh    = (const float*)d_in[9];
    const float* Wa      = (const float*)d_in[10];
    const float* Ua      = (const float*)d_in[11];
    const float* va      = (const float*)d_in[12];
    const float* mo_w    = (const float*)d_in[13];
    const float* mo_b    = (const float*)d_in[14];
    const float* fc_w    = (const float*)d_in[15];
    const float* fc_b    = (const float*)d_in[16];

    float* logits = (float*)d_out;                       // [B,T,V]
    float* alphas = logits + (size_t)Bc*Tc*Vc;           // [B,T,T]

    float *psiT, *phidT, *pencT, *pUa, *psWa, *pxT, *pmoinT, *pgxT, *pghT, *pmT;
    cudaGetSymbolAddress((void**)&psiT,   g_siT);
    cudaGetSymbolAddress((void**)&phidT,  g_hidT);
    cudaGetSymbolAddress((void**)&pencT,  g_encT);
    cudaGetSymbolAddress((void**)&pUa,    g_Ua);
    cudaGetSymbolAddress((void**)&psWa,   g_sWa);
    cudaGetSymbolAddress((void**)&pxT,    g_xT);
    cudaGetSymbolAddress((void**)&pmoinT, g_moinT);
    cudaGetSymbolAddress((void**)&pgxT,   g_gxT);
    cudaGetSymbolAddress((void**)&pghT,   g_ghT);
    cudaGetSymbolAddress((void**)&pmT,    g_mT);

    // ---- one-time setup
    to_p4<<<dim3(4, 1), 256>>>(hidden + Bc*Hc, phidT, Hc);              // hidden[1] -> P4
    to_p4<<<dim3(8, (Bc*Tc)/32), 256>>>(enc_out, pencT, 2*Hc);          // enc_out -> P4
    // si0 = tanh(hidden1 @ Ws_w^T + Ws_b)
    gemmP4<Hc,2,0><<<dim3(Hc/16, 1), 64>>>(phidT, Ws_w, Ws_b, psiT, nullptr, 0, 1);
    // Ua_enc = enc_out @ Ua^T  (row-major [bt][a])
    gemmP4<2*Hc,4,1><<<dim3(Hc/32, (Bc*Tc)/32), 128>>>(pencT, Ua, nullptr, pUa, nullptr, Hc, 0);

    for (int t = 0; t < Tc; t++){
        // sWa = si @ Wa^T  (row-major [b][a])
        gemmP4<Hc,2,1><<<dim3(Hc/16, 1), 64>>>(psiT, Wa, nullptr, psWa, nullptr, Hc, 0);
        attn_e_kernel<<<dim3(Tc, Bc), 128>>>(va);
        attn_ctx_kernel<<<Bc, 256>>>(enc_out, alphas, t);
        // yi_emb = yi @ emb_w^T + emb_b  (yi == si carry; zero at t=0)
        gemmP4<Hc,2,0><<<dim3(Ec/16, 1), 64>>>(t == 0 ? nullptr : psiT, emb_w, emb_b,
                                               pxT, pmoinT + (size_t)3*Hc*32, 0, 0);
        // gx = x @ w_ih^T + b_ih ; gh = si @ w_hh^T + b_hh
        gemmP4<2*Hc+Ec,4,0><<<dim3(3*Hc/32, 1), 128>>>(pxT, w_ih, b_ih, pgxT, nullptr, 0, 0);
        gemmP4<Hc,4,0><<<dim3(3*Hc/32, 1), 128>>>(psiT, w_hh, b_hh, pghT, nullptr, 0, 0);
        gru_gate_kernel<<<(Hc*32 + 255)/256, 256>>>();
        // maxout: m = maxpair(moin @ mo_w^T + mo_b) -> P4
        gemmP4<3*Hc+Ec,4,2><<<dim3(2*Mc/32, 1), 128>>>(pmoinT, mo_w, mo_b, pmT, nullptr, 0, 0);
        // logits[:, t, :] = m @ fc_w^T + fc_b   (row-major, row stride T*V)
        gemmP4<Mc,4,1><<<dim3(Vc/32, 1), 128>>>(pmT, fc_w, fc_b,
                                                logits + (size_t)t*Vc, nullptr, Tc*Vc, 0);
    }
}

// round 3
// speedup vs baseline: 4.9877x; 3.7770x over previous
#include <cuda_runtime.h>
#include <math.h>

#define Bc 32
#define Tc 64
#define Hc 1024
#define Ec 512
#define Mc 512
#define Vc 32000

// ---------------- scratch (device globals) ------------------------------------
// P4 layout: arr[(k>>2)*128 + b*4 + (k&3)]  (k = feature, b = batch lane 0..31)
__device__ float g_siT[Hc*32];
__device__ float g_hidT[Hc*32];
__device__ float g_encT[Bc*Tc*2*Hc];        // enc_out P4, 64 row-groups
__device__ float g_Ua[Bc*Tc*Hc];            // row-major [bt][a]
__device__ float g_sWa[Bc*Hc];              // row-major [b][a]
__device__ float g_e[Bc*Tc];
__device__ float g_xT[(2*Hc+Ec)*32];        // P4: [emb(512) | ctx(2048)]
__device__ float g_moinT[(3*Hc+Ec)*32];     // P4: [si(1024) | ctx(2048) | emb(512)]
__device__ float g_mT[Mc*32];
__device__ float g_partA[8*3*Hc*32];        // split-K partials (gx / mo)
__device__ float g_partB[4*3*Hc*32];        // split-K partials (gh)

typedef unsigned long long ull;
typedef unsigned int uint;

__device__ __forceinline__ ull pk2(float x, float y){
    ull r; asm("mov.b64 %0, {%1, %2};" : "=l"(r) : "f"(x), "f"(y)); return r;
}
__device__ __forceinline__ float2 upk2(ull p){
    float2 f; asm("mov.b64 {%0, %1}, %2;" : "=f"(f.x), "=f"(f.y) : "l"(p)); return f;
}
__device__ __forceinline__ void fma2(ull &d, ull a, ull b){
    asm("fma.rn.f32x2 %0, %1, %2, %0;" : "+l"(d) : "l"(a), "l"(b));
}
__device__ __forceinline__ float tanha(float x){
    float y; asm("tanh.approx.f32 %0, %1;" : "=f"(y) : "f"(x)); return y;
}
__device__ __forceinline__ void cpa16(uint s, const void* g){
    asm volatile("cp.async.cg.shared.global [%0], [%1], 16;" :: "r"(s), "l"(g));
}
__device__ __forceinline__ void cpa_commit(){
    asm volatile("cp.async.commit_group;");
}

// ---------------- row-major [rows][K] -> P4 (row-groups of 32) ----------------
__global__ void to_p4(const float* __restrict__ in, float* __restrict__ out, int K){
    int g = blockIdx.y;
    int n4 = (K >> 2) * 32;
    for (int idx = blockIdx.x*blockDim.x + threadIdx.x; idx < n4; idx += gridDim.x*blockDim.x){
        int lane = idx & 31, k4 = idx >> 5;
        float4 v = *(const float4*)(in + (size_t)(g*32 + lane)*K + k4*4);
        *(float4*)(out + (size_t)g*K*32 + k4*128 + lane*4) = v;
    }
}

// ---------------- smem-staged GEMM --------------------------------------------
// out[row=lane, col] = act( A_P4[row,:] . W[col,:] + bias[col] )
// 256 threads, 8 warps x 8 cols = 64-col tile; BK=64; cp.async double buffer.
// MODE 0: P4 store (+ optional dup to out2, pre-offset)
// MODE 1: row-major via smem transpose (ldo = row stride, rowBase = blockIdx.y*32)
// MODE 3: split-K partial: out[(z*N + col)*32 + lane] (no bias/act)
template<int KTOT, int SPLITK, int MODE>
__global__ void gemmT(const float* __restrict__ A, const float* __restrict__ W,
                      const float* __restrict__ bias,
                      float* __restrict__ out, float* __restrict__ out2,
                      int ldo, int act)
{
    __shared__ float ws[2][64][64];
    const int tid  = threadIdx.x;
    const int lane = tid & 31;
    const int warp = tid >> 5;
    const int colBase = blockIdx.x * 64;
    constexpr int NT = KTOT / 64;
    constexpr int TZ = NT / SPLITK;
    const int t0 = (SPLITK > 1) ? blockIdx.z * TZ : 0;

    ull acc[8];
#pragma unroll
    for (int v = 0; v < 8; v++) acc[v] = 0ull;

    if (A){
        const float* aP = A + (size_t)blockIdx.y*KTOT*32 + lane*4;
        // prefetch tile t0 into buf 0
        {
#pragma unroll
            for (int i = 0; i < 4; i++){
                int f = tid + i*256;
                int c = f >> 4, kf = f & 15;
                cpa16((uint)__cvta_generic_to_shared(&ws[0][c][kf*4]),
                      W + (size_t)(colBase + c)*KTOT + (size_t)t0*64 + kf*4);
            }
            cpa_commit();
        }
        for (int t = 0; t < TZ; t++){
            if (t + 1 < TZ){
#pragma unroll
                for (int i = 0; i < 4; i++){
                    int f = tid + i*256;
                    int c = f >> 4, kf = f & 15;
                    cpa16((uint)__cvta_generic_to_shared(&ws[(t+1)&1][c][kf*4]),
                          W + (size_t)(colBase + c)*KTOT + (size_t)(t0+t+1)*64 + kf*4);
                }
                cpa_commit();
                asm volatile("cp.async.wait_group 1;");
            } else {
                asm volatile("cp.async.wait_group 0;");
            }
            __syncthreads();
            const float* aT = aP + (size_t)(t0 + t)*16*128;
            const float (*wb)[64] = ws[t & 1];
#pragma unroll
            for (int k4 = 0; k4 < 16; k4++){
                float4 a4 = *(const float4*)(aT + k4*128);
                ull a01 = pk2(a4.x, a4.y);
                ull a23 = pk2(a4.z, a4.w);
#pragma unroll
                for (int v = 0; v < 8; v++){
                    float4 w4 = *(const float4*)(&wb[warp*8 + v][k4*4]);
                    fma2(acc[v], pk2(w4.x, w4.y), a01);
                    fma2(acc[v], pk2(w4.z, w4.w), a23);
                }
            }
            __syncthreads();
        }
    }

    const int col0 = colBase + warp*8;

    if (MODE == 3){
        const int N = gridDim.x * 64;
        float* p = out + ((size_t)blockIdx.z*N + col0)*32 + lane;
#pragma unroll
        for (int v = 0; v < 8; v++){
            float2 f = upk2(acc[v]);
            p[v*32] = f.x + f.y;
        }
        return;
    }

    float res[8];
#pragma unroll
    for (int v = 0; v < 8; v++){
        float2 f = upk2(acc[v]);
        res[v] = f.x + f.y + (bias ? bias[col0 + v] : 0.f);
        if (act) res[v] = tanhf(res[v]);
    }

    if (MODE == 0){
        size_t idx = (size_t)(col0 >> 2)*128 + lane*4;
        *(float4*)(out + idx)       = make_float4(res[0], res[1], res[2], res[3]);
        *(float4*)(out + idx + 128) = make_float4(res[4], res[5], res[6], res[7]);
        if (out2){
            *(float4*)(out2 + idx)       = make_float4(res[0], res[1], res[2], res[3]);
            *(float4*)(out2 + idx + 128) = make_float4(res[4], res[5], res[6], res[7]);
        }
    } else { // MODE 1: transpose via smem (stride 33), coalesced row-major store
        float* st = (float*)ws;
        __syncthreads();
#pragma unroll
        for (int v = 0; v < 8; v++)
            st[(warp*8 + v)*33 + lane] = res[v];
        __syncthreads();
        int row = tid >> 3;
        int cg  = (tid & 7) * 8;
        float4 o0 = make_float4(st[(cg+0)*33 + row], st[(cg+1)*33 + row],
                                st[(cg+2)*33 + row], st[(cg+3)*33 + row]);
        float4 o1 = make_float4(st[(cg+4)*33 + row], st[(cg+5)*33 + row],
                                st[(cg+6)*33 + row], st[(cg+7)*33 + row]);
        size_t ob = (size_t)(blockIdx.y*32 + row)*ldo + colBase + cg;
        *(float4*)(out + ob)     = o0;
        *(float4*)(out + ob + 4) = o1;
    }
}

// ---------------- attention ---------------------------------------------------
__global__ void attn_e_kernel(const float* __restrict__ va){
    int b  = blockIdx.y;
    int bt = b*Tc + blockIdx.x;
    const float* sw = g_sWa + (size_t)b*Hc;
    const float* ua = g_Ua  + (size_t)bt*Hc;
    float p = 0.f;
    for (int a = threadIdx.x; a < Hc; a += 128)
        p += va[a] * tanha(sw[a] + ua[a]);
    __shared__ float red[4];
#pragma unroll
    for (int o = 16; o > 0; o >>= 1) p += __shfl_xor_sync(0xffffffffu, p, o);
    if ((threadIdx.x & 31) == 0) red[threadIdx.x >> 5] = p;
    __syncthreads();
    if (threadIdx.x == 0) g_e[bt] = red[0] + red[1] + red[2] + red[3];
}

__global__ void attn_ctx_kernel(const float* __restrict__ enc_out,
                                float* __restrict__ alphas, int tstep){
    int b = blockIdx.x;
    __shared__ float sal[Tc];
    __shared__ float sinv;
    if (threadIdx.x == 0){
        float mx = -1e30f;
        for (int t = 0; t < Tc; t++) mx = fmaxf(mx, g_e[b*Tc + t]);
        float s = 0.f;
        for (int t = 0; t < Tc; t++){ float ev = __expf(g_e[b*Tc + t] - mx); sal[t] = ev; s += ev; }
        sinv = 1.f / s;
    }
    __syncthreads();
    if (threadIdx.x < Tc) sal[threadIdx.x] *= sinv;
    __syncthreads();
    if (threadIdx.x < Tc)
        alphas[((size_t)b*Tc + tstep)*Tc + threadIdx.x] = sal[threadIdx.x];

    const float4* eo = (const float4*)(enc_out + (size_t)b*Tc*2*Hc);
    for (int f4 = threadIdx.x; f4 < (2*Hc)/4; f4 += blockDim.x){
        float4 acc = make_float4(0.f, 0.f, 0.f, 0.f);
        for (int t = 0; t < Tc; t++){
            float al = sal[t];
            float4 ev = eo[(size_t)t*(2*Hc/4) + f4];
            acc.x += al*ev.x; acc.y += al*ev.y; acc.z += al*ev.z; acc.w += al*ev.w;
        }
        *(float4*)&g_xT[(size_t)(Ec/4 + f4)*128 + b*4]    = acc;
        *(float4*)&g_moinT[(size_t)(Hc/4 + f4)*128 + b*4] = acc;
    }
}

// ---------------- fused split-K reduce + GRU gates ----------------------------
__global__ void gru_fused(const float* __restrict__ b_ih, const float* __restrict__ b_hh){
    int j = blockIdx.x*256 + threadIdx.x;           // Hc*32 elems
    if (j >= Hc*32) return;
    int lane = j & 31, col = j >> 5;
    float xr = 0.f, xz = 0.f, xn = 0.f, hr = 0.f, hz = 0.f, hn = 0.f;
#pragma unroll
    for (int z = 0; z < 4; z++){
        size_t ba = (size_t)z*3*Hc*32;
        xr += g_partA[ba + (size_t)(col)*32        + lane];
        xz += g_partA[ba + (size_t)(Hc + col)*32   + lane];
        xn += g_partA[ba + (size_t)(2*Hc + col)*32 + lane];
        hr += g_partB[ba + (size_t)(col)*32        + lane];
        hz += g_partB[ba + (size_t)(Hc + col)*32   + lane];
        hn += g_partB[ba + (size_t)(2*Hc + col)*32 + lane];
    }
    xr += b_ih[col];        hr += b_hh[col];
    xz += b_ih[Hc + col];   hz += b_hh[Hc + col];
    xn += b_ih[2*Hc + col]; hn += b_hh[2*Hc + col];
    float r = 1.f/(1.f + __expf(-(xr + hr)));
    float z = 1.f/(1.f + __expf(-(xz + hz)));
    float n = tanhf(xn + r*hn);
    size_t p4 = (size_t)(col >> 2)*128 + lane*4 + (col & 3);
    float s  = g_siT[p4];
    float sn = (1.f - z)*n + z*s;
    g_siT[p4]   = sn;
    g_moinT[p4] = sn;
}

// ---------------- fused split-K reduce + maxout -------------------------------
__global__ void mo_reduce(const float* __restrict__ mo_b){
    int j = blockIdx.x*256 + threadIdx.x;           // Mc*32 elems
    if (j >= Mc*32) return;
    int lane = j & 31, m = j >> 5;
    float s0 = 0.f, s1 = 0.f;
#pragma unroll
    for (int z = 0; z < 8; z++){
        size_t ba = (size_t)z*2*Mc*32;
        s0 += g_partA[ba + (size_t)(2*m)*32   + lane];
        s1 += g_partA[ba + (size_t)(2*m+1)*32 + lane];
    }
    float val = fmaxf(s0 + mo_b[2*m], s1 + mo_b[2*m + 1]);
    g_mT[(size_t)(m >> 2)*128 + lane*4 + (m & 3)] = val;
}

// ---------------- launch ------------------------------------------------------
extern "C" void kernel_launch(void* const* d_in, const int* in_sizes, int n_in,
                              void* d_out, int out_size)
{
    const float* enc_out = (const float*)d_in[0];
    const float* hidden  = (const float*)d_in[1];
    const float* Ws_w    = (const float*)d_in[2];
    const float* Ws_b    = (const float*)d_in[3];
    const float* emb_w   = (const float*)d_in[4];
    const float* emb_b   = (const float*)d_in[5];
    const float* w_ih    = (const float*)d_in[6];
    const float* w_hh    = (const float*)d_in[7];
    const float* b_ih    = (const float*)d_in[8];
    const float* b_hh    = (const float*)d_in[9];
    const float* Wa      = (const float*)d_in[10];
    const float* Ua      = (const float*)d_in[11];
    const float* va      = (const float*)d_in[12];
    const float* mo_w    = (const float*)d_in[13];
    const float* mo_b    = (const float*)d_in[14];
    const float* fc_w    = (const float*)d_in[15];
    const float* fc_b    = (const float*)d_in[16];

    float* logits = (float*)d_out;                       // [B,T,V]
    float* alphas = logits + (size_t)Bc*Tc*Vc;           // [B,T,T]

    float *psiT, *phidT, *pencT, *pUa, *psWa, *pxT, *pmoinT, *pmT, *ppA, *ppB;
    cudaGetSymbolAddress((void**)&psiT,   g_siT);
    cudaGetSymbolAddress((void**)&phidT,  g_hidT);
    cudaGetSymbolAddress((void**)&pencT,  g_encT);
    cudaGetSymbolAddress((void**)&pUa,    g_Ua);
    cudaGetSymbolAddress((void**)&psWa,   g_sWa);
    cudaGetSymbolAddress((void**)&pxT,    g_xT);
    cudaGetSymbolAddress((void**)&pmoinT, g_moinT);
    cudaGetSymbolAddress((void**)&pmT,    g_mT);
    cudaGetSymbolAddress((void**)&ppA,    g_partA);
    cudaGetSymbolAddress((void**)&ppB,    g_partB);

    // ---- one-time setup
    to_p4<<<dim3(4, 1), 256>>>(hidden + Bc*Hc, phidT, Hc);
    to_p4<<<dim3(8, (Bc*Tc)/32), 256>>>(enc_out, pencT, 2*Hc);
    // si0 = tanh(hidden1 @ Ws_w^T + Ws_b) -> P4
    gemmT<Hc,1,0><<<dim3(Hc/64, 1), 256>>>(phidT, Ws_w, Ws_b, psiT, nullptr, 0, 1);
    // Ua_enc = enc_out @ Ua^T -> row-major [bt][a]
    gemmT<2*Hc,1,1><<<dim3(Hc/64, (Bc*Tc)/32), 256>>>(pencT, Ua, nullptr, pUa, nullptr, Hc, 0);

    for (int t = 0; t < Tc; t++){
        // sWa = si @ Wa^T -> row-major [b][a]
        gemmT<Hc,1,1><<<dim3(Hc/64, 1), 256>>>(psiT, Wa, nullptr, psWa, nullptr, Hc, 0);
        attn_e_kernel<<<dim3(Tc, Bc), 128>>>(va);
        attn_ctx_kernel<<<Bc, 256>>>(enc_out, alphas, t);
        // yi_emb = yi @ emb_w^T + emb_b -> xT[0:E] and moinT[3H:3H+E] (P4 dual)
        gemmT<Hc,1,0><<<dim3(Ec/64, 1), 256>>>(t == 0 ? nullptr : psiT, emb_w, emb_b,
                                               pxT, pmoinT + (size_t)3*Hc*32, 0, 0);
        // gx partials (split-K 4) ; gh partials (split-K 4)
        gemmT<2*Hc+Ec,4,3><<<dim3(3*Hc/64, 1, 4), 256>>>(pxT,  w_ih, nullptr, ppA, nullptr, 0, 0);
        gemmT<Hc,     4,3><<<dim3(3*Hc/64, 1, 4), 256>>>(psiT, w_hh, nullptr, ppB, nullptr, 0, 0);
        // fused reduce + GRU gates -> siT, moinT[0:H]
        gru_fused<<<(Hc*32 + 255)/256, 256>>>(b_ih, b_hh);
        // maxout GEMM partials (split-K 8) + fused reduce/maxout -> mT
        gemmT<3*Hc+Ec,8,3><<<dim3(2*Mc/64, 1, 8), 256>>>(pmoinT, mo_w, nullptr, ppA, nullptr, 0, 0);
        mo_reduce<<<(Mc*32 + 255)/256, 256>>>(mo_b);
        // logits[:, t, :] = m @ fc_w^T + fc_b (row-major, row stride T*V)
        gemmT<Mc,1,1><<<dim3(Vc/64, 1), 256>>>(pmT, fc_w, fc_b,
                                               logits + (size_t)t*Vc, nullptr, Tc*Vc, 0);
    }
}